// round 2
// baseline (speedup 1.0000x reference)
#include <cuda_runtime.h>

// ---------------------------------------------------------------------------
// MultitaskSNN: T=50 sequential LIF scan, 5 tiny dense layers, B=32768 lanes.
// One thread processes TWO batch elements via packed f32x2 math.
// Weights duplicated {w,w} in SMEM; LDS.128 feeds two packed FMAs per load.
// Per-layer outputs are stored immediately to keep register pressure < 255.
// ---------------------------------------------------------------------------

typedef unsigned long long u64;

#define TT 50
#define NIN 32
#define NSH 28
#define NCH 8
#define NCO 3
#define NRH 14

// smem u64 layout offsets (weights rows are even-length, so LDS.128 alignment
// holds when the row base offset is even; all row bases below are even).
#define OW_SH 0        // 28*32 = 896
#define OB_SH 896      // 28
#define OW_CH 924      // 8*28 = 224
#define OB_CH 1148     // 8
#define OW_CO 1156     // 3*8 = 24
#define OB_CO 1180     // 3  (pad next to even)
#define OW_RH 1184     // 14*28 = 392
#define OB_RH 1576     // 14
#define OW_RO 1590     // 14
#define OB_RO 1604     // 1
#define SW_TOTAL 1606

__device__ __forceinline__ u64 pack2(float lo, float hi) {
    u64 r;
    asm("mov.b64 %0, {%1, %2};" : "=l"(r) : "f"(lo), "f"(hi));
    return r;
}
__device__ __forceinline__ void unpack2(u64 v, float& lo, float& hi) {
    asm("mov.b64 {%0, %1}, %2;" : "=f"(lo), "=f"(hi) : "l"(v));
}
__device__ __forceinline__ u64 fma2(u64 a, u64 b, u64 c) {
    u64 d;
    asm("fma.rn.f32x2 %0, %1, %2, %3;" : "=l"(d) : "l"(a), "l"(b), "l"(c));
    return d;
}
__device__ __forceinline__ u64 add2(u64 a, u64 b) {
    u64 d;
    asm("add.rn.f32x2 %0, %1, %2;" : "=l"(d) : "l"(a), "l"(b));
    return d;
}

#define BETA2 0x3F6666663F666666ull  // {0.9f, 0.9f}

// LIF (snntorch Leaky, reset='subtract'):
//   reset = (m_prev > 1);  m = 0.9*m_prev + cur - reset;  spk = (m > 1)
__device__ __forceinline__ u64 lif2(u64& m2, u64 cur2) {
    float m0, m1;
    unpack2(m2, m0, m1);
    float r0 = (m0 > 1.0f) ? -1.0f : 0.0f;
    float r1 = (m1 > 1.0f) ? -1.0f : 0.0f;
    m2 = add2(fma2(BETA2, m2, cur2), pack2(r0, r1));
    float n0, n1;
    unpack2(m2, n0, n1);
    float s0 = (n0 > 1.0f) ? 1.0f : 0.0f;
    float s1 = (n1 > 1.0f) ? 1.0f : 0.0f;
    return pack2(s0, s1);
}

// dot over NSH packed spikes with LDS.128 weight loads (row base even)
__device__ __forceinline__ u64 dot28(const u64* __restrict__ sps,
                                     const u64* __restrict__ wrow, u64 acc) {
#pragma unroll
    for (int i = 0; i < NSH; i += 2) {
        ulonglong2 w = *(const ulonglong2*)(wrow + i);
        acc = fma2(sps[i], w.x, acc);
        acc = fma2(sps[i + 1], w.y, acc);
    }
    return acc;
}

__global__ __launch_bounds__(128, 1) void snn_kernel(
    const float* __restrict__ x,
    const float* __restrict__ Wsh, const float* __restrict__ bsh,
    const float* __restrict__ Wch, const float* __restrict__ bch,
    const float* __restrict__ Wco, const float* __restrict__ bco,
    const float* __restrict__ Wrh, const float* __restrict__ brh,
    const float* __restrict__ Wro, const float* __restrict__ bro,
    float* __restrict__ out, int B)
{
    __shared__ u64 sw[SW_TOTAL];
    const int tid = threadIdx.x;

    // Stage weights duplicated {w,w}
    for (int i = tid; i < NSH * NIN; i += 128) sw[OW_SH + i] = pack2(Wsh[i], Wsh[i]);
    for (int i = tid; i < NSH;       i += 128) sw[OB_SH + i] = pack2(bsh[i], bsh[i]);
    for (int i = tid; i < NCH * NSH; i += 128) sw[OW_CH + i] = pack2(Wch[i], Wch[i]);
    for (int i = tid; i < NCH;       i += 128) sw[OB_CH + i] = pack2(bch[i], bch[i]);
    for (int i = tid; i < NCO * NCH; i += 128) sw[OW_CO + i] = pack2(Wco[i], Wco[i]);
    for (int i = tid; i < NCO;       i += 128) sw[OB_CO + i] = pack2(bco[i], bco[i]);
    for (int i = tid; i < NRH * NSH; i += 128) sw[OW_RH + i] = pack2(Wrh[i], Wrh[i]);
    for (int i = tid; i < NRH;       i += 128) sw[OB_RH + i] = pack2(brh[i], brh[i]);
    for (int i = tid; i < NRH;       i += 128) sw[OW_RO + i] = pack2(Wro[i], Wro[i]);
    if (tid == 0) sw[OB_RO] = pack2(bro[0], bro[0]);
    __syncthreads();

    const int pair = blockIdx.x * 128 + tid;
    if (pair * 2 >= B) return;
    const int b0 = pair * 2;

    // Packed membrane states (lo = batch b0, hi = batch b0+1)
    u64 m_sh[NSH], m_ch[NCH], m_co[NCO], m_rh[NRH], m_ro;
#pragma unroll
    for (int o = 0; o < NSH; o++) m_sh[o] = 0ull;
#pragma unroll
    for (int o = 0; o < NCH; o++) m_ch[o] = 0ull;
#pragma unroll
    for (int o = 0; o < NCO; o++) m_co[o] = 0ull;
#pragma unroll
    for (int o = 0; o < NRH; o++) m_rh[o] = 0ull;
    m_ro = 0ull;

    const float* xbase = x + (size_t)b0 * NIN;
    const size_t TB = (size_t)TT * B;
    float* p_mco = out + (size_t)b0 * NCO;             // section 0: [T,B,3]
    float* p_sch = out + TB * 3  + (size_t)b0 * NCH;   // section 1: [T,B,8]
    float* p_mro = out + TB * 11 + (size_t)b0;         // section 2: [T,B,1]
    float* p_srh = out + TB * 12 + (size_t)b0 * NRH;   // section 3: [T,B,14]
    float* p_ssh = out + TB * 26 + (size_t)b0 * NSH;   // section 4: [T,B,28]

    const size_t xstep = (size_t)B * NIN;

#pragma unroll 1
    for (int t = 0; t < TT; t++) {
        const float* xp = xbase + (size_t)t * xstep;

        // Prefetch next step's x (each elem = 32 floats = one 128B line)
        if (t + 1 < TT) {
            const float* xn = xp + xstep;
            asm volatile("prefetch.global.L2 [%0];" :: "l"(xn));
            asm volatile("prefetch.global.L2 [%0];" :: "l"(xn + NIN));
        }

        // ---- Layer 1: shared hidden (28 <- 32), chunked over i ----
        u64 acc[NSH];
#pragma unroll
        for (int o = 0; o < NSH; o++) acc[o] = 0ull;
#pragma unroll
        for (int ic = 0; ic < 4; ic++) {
            const float4 a0 = *(const float4*)(xp + ic * 8);
            const float4 a1 = *(const float4*)(xp + ic * 8 + 4);
            const float4 c0 = *(const float4*)(xp + NIN + ic * 8);
            const float4 c1 = *(const float4*)(xp + NIN + ic * 8 + 4);
            u64 x2[8];
            x2[0] = pack2(a0.x, c0.x); x2[1] = pack2(a0.y, c0.y);
            x2[2] = pack2(a0.z, c0.z); x2[3] = pack2(a0.w, c0.w);
            x2[4] = pack2(a1.x, c1.x); x2[5] = pack2(a1.y, c1.y);
            x2[6] = pack2(a1.z, c1.z); x2[7] = pack2(a1.w, c1.w);
#pragma unroll
            for (int o = 0; o < NSH; o++) {
                const u64* wrow = &sw[OW_SH + o * NIN + ic * 8];
#pragma unroll
                for (int j = 0; j < 8; j += 2) {
                    ulonglong2 w = *(const ulonglong2*)(wrow + j);
                    acc[o] = fma2(x2[j], w.x, acc[o]);
                    acc[o] = fma2(x2[j + 1], w.y, acc[o]);
                }
            }
        }
        u64 sps[NSH];
#pragma unroll
        for (int o = 0; o < NSH; o++)
            sps[o] = lif2(m_sh[o], add2(acc[o], sw[OB_SH + o]));

        // store spk_sh immediately: [lo x28][hi x28], 16B-aligned
        {
            float* p = p_ssh + (size_t)t * B * NSH;
#pragma unroll
            for (int k = 0; k < 7; k++) {
                float a, b, c, d, e, f, g, h;
                unpack2(sps[4 * k + 0], a, e);
                unpack2(sps[4 * k + 1], b, f);
                unpack2(sps[4 * k + 2], c, g);
                unpack2(sps[4 * k + 3], d, h);
                ((float4*)p)[k]     = make_float4(a, b, c, d);
                ((float4*)p)[k + 7] = make_float4(e, f, g, h);
            }
        }

        // ---- Layer 2: class hidden (8 <- 28) ----
        u64 spc[NCH];
#pragma unroll
        for (int o = 0; o < NCH; o++) {
            u64 a = dot28(sps, &sw[OW_CH + o * NSH], 0ull);
            spc[o] = lif2(m_ch[o], add2(a, sw[OB_CH + o]));
        }
        // store spk_ch: [lo x8][hi x8], 64B-aligned
        {
            float* p = p_sch + (size_t)t * B * NCH;
#pragma unroll
            for (int k = 0; k < 2; k++) {
                float a, b, c, d, e, f, g, h;
                unpack2(spc[4 * k + 0], a, e);
                unpack2(spc[4 * k + 1], b, f);
                unpack2(spc[4 * k + 2], c, g);
                unpack2(spc[4 * k + 3], d, h);
                ((float4*)p)[k]     = make_float4(a, b, c, d);
                ((float4*)p)[k + 2] = make_float4(e, f, g, h);
            }
        }

        // ---- Layer 3: class out (3 <- 8), only membrane recorded ----
#pragma unroll
        for (int o = 0; o < NCO; o++) {
            u64 a = 0ull;
#pragma unroll
            for (int i = 0; i < NCH; i++)
                a = fma2(spc[i], sw[OW_CO + o * NCH + i], a);
            (void)lif2(m_co[o], add2(a, sw[OB_CO + o]));
        }
        // store m_co: 6 floats, 8B-aligned
        {
            float a0, a1, c0, c1, d0, d1;
            unpack2(m_co[0], a0, a1);
            unpack2(m_co[1], c0, c1);
            unpack2(m_co[2], d0, d1);
            float* p = p_mco + (size_t)t * B * NCO;
            ((float2*)p)[0] = make_float2(a0, c0);
            ((float2*)p)[1] = make_float2(d0, a1);
            ((float2*)p)[2] = make_float2(c1, d1);
        }

        // ---- Layer 4: reg hidden (14 <- 28) ----
        u64 spr[NRH];
#pragma unroll
        for (int o = 0; o < NRH; o++) {
            u64 a = dot28(sps, &sw[OW_RH + o * NSH], 0ull);
            spr[o] = lif2(m_rh[o], add2(a, sw[OB_RH + o]));
        }
        // store spk_rh: [lo x14][hi x14], base 16B-aligned (28*4*pair = 112B*pair)
        // lo occupies floats [0,14), hi [14,28): use float2 stores to keep alignment simple
        {
            float* p = p_srh + (size_t)t * B * NRH;
#pragma unroll
            for (int k = 0; k < 7; k++) {
                float a, b, e, f;
                unpack2(spr[2 * k + 0], a, e);
                unpack2(spr[2 * k + 1], b, f);
                ((float2*)p)[k]     = make_float2(a, b);
                ((float2*)p)[k + 7] = make_float2(e, f);
            }
        }

        // ---- Layer 5: reg out (1 <- 14), only membrane recorded ----
        {
            u64 a = 0ull;
#pragma unroll
            for (int i = 0; i < NRH; i++)
                a = fma2(spr[i], sw[OW_RO + i], a);
            (void)lif2(m_ro, add2(a, sw[OB_RO]));
            float r0, r1;
            unpack2(m_ro, r0, r1);
            *(float2*)(p_mro + (size_t)t * B) = make_float2(r0, r1);
        }
    }
}

extern "C" void kernel_launch(void* const* d_in, const int* in_sizes, int n_in,
                              void* d_out, int out_size) {
    const float* x   = (const float*)d_in[0];
    const float* Wsh = (const float*)d_in[1];
    const float* bsh = (const float*)d_in[2];
    const float* Wch = (const float*)d_in[3];
    const float* bch = (const float*)d_in[4];
    const float* Wco = (const float*)d_in[5];
    const float* bco = (const float*)d_in[6];
    const float* Wrh = (const float*)d_in[7];
    const float* brh = (const float*)d_in[8];
    const float* Wro = (const float*)d_in[9];
    const float* bro = (const float*)d_in[10];

    const int B = in_sizes[0] / (TT * NIN);
    const int pairs = B / 2;
    const int blocks = (pairs + 127) / 128;

    snn_kernel<<<blocks, 128>>>(x, Wsh, bsh, Wch, bch, Wco, bco,
                                Wrh, brh, Wro, bro, (float*)d_out, B);
}

// round 3
// speedup vs baseline: 2.4527x; 2.4527x over previous
#include <cuda_runtime.h>

// ---------------------------------------------------------------------------
// MultitaskSNN: T=50 sequential LIF scan, 5 tiny dense layers, B=32768 lanes.
// Round 3: one batch element per thread (scalar fp32), 224-thread CTAs so all
// 148 SMs get exactly one CTA (7 warps/SM -> ~1.75 warps/SMSP). x is register
// double-buffered across t; weights in SMEM read via broadcast LDS.128;
// outputs stored streaming (__stcs). Arithmetic order matches XLA bit-exactly.
// ---------------------------------------------------------------------------

#define TT 50
#define NIN 32
#define NSH 28
#define NCH 8
#define NCO 3
#define NRH 14

// smem float offsets (all weight-row bases 16B aligned for LDS.128)
#define OW_SH 0        // 28*32 = 896
#define OB_SH 896      // 28
#define OW_CH 924      // 8*28 = 224   (924*4=3696, 16B aligned; rows +112B)
#define OB_CH 1148     // 8
#define OW_CO 1156     // 3*8 = 24     (4624, aligned; rows +32B)
#define OB_CO 1180     // 3
#define OW_RH 1184     // 14*28 = 392  (4736, aligned)
#define OB_RH 1576     // 14
#define OW_RO 1592     // 14           (6368, aligned)
#define OB_RO 1606     // 1
#define SW_TOTAL 1607

#define THREADS 224

// LIF (snntorch Leaky, reset='subtract'), rounding matches the reference:
//   reset = (m_prev > 1);  m = fma(0.9, m_prev, cur) - reset;  spk = (m > 1)
__device__ __forceinline__ float lif(float& m, float cur) {
    float r = (m > 1.0f) ? 1.0f : 0.0f;
    m = __fmaf_rn(0.9f, m, cur) - r;
    return (m > 1.0f) ? 1.0f : 0.0f;
}

// ascending-i dot over 28 spike scalars, weights via float4 broadcast LDS
__device__ __forceinline__ float dot28(const float* __restrict__ sps,
                                       const float* __restrict__ wrow) {
    float a = 0.0f;
#pragma unroll
    for (int k = 0; k < 7; k++) {
        float4 w = *(const float4*)(wrow + 4 * k);
        a = __fmaf_rn(sps[4 * k + 0], w.x, a);
        a = __fmaf_rn(sps[4 * k + 1], w.y, a);
        a = __fmaf_rn(sps[4 * k + 2], w.z, a);
        a = __fmaf_rn(sps[4 * k + 3], w.w, a);
    }
    return a;
}

__global__ __launch_bounds__(THREADS, 1) void snn_kernel(
    const float* __restrict__ x,
    const float* __restrict__ Wsh, const float* __restrict__ bsh,
    const float* __restrict__ Wch, const float* __restrict__ bch,
    const float* __restrict__ Wco, const float* __restrict__ bco,
    const float* __restrict__ Wrh, const float* __restrict__ brh,
    const float* __restrict__ Wro, const float* __restrict__ bro,
    float* __restrict__ out, int B)
{
    __shared__ float sw[SW_TOTAL];
    const int tid = threadIdx.x;

    for (int i = tid; i < NSH * NIN; i += THREADS) sw[OW_SH + i] = Wsh[i];
    for (int i = tid; i < NSH;       i += THREADS) sw[OB_SH + i] = bsh[i];
    for (int i = tid; i < NCH * NSH; i += THREADS) sw[OW_CH + i] = Wch[i];
    for (int i = tid; i < NCH;       i += THREADS) sw[OB_CH + i] = bch[i];
    for (int i = tid; i < NCO * NCH; i += THREADS) sw[OW_CO + i] = Wco[i];
    for (int i = tid; i < NCO;       i += THREADS) sw[OB_CO + i] = bco[i];
    for (int i = tid; i < NRH * NSH; i += THREADS) sw[OW_RH + i] = Wrh[i];
    for (int i = tid; i < NRH;       i += THREADS) sw[OB_RH + i] = brh[i];
    for (int i = tid; i < NRH;       i += THREADS) sw[OW_RO + i] = Wro[i];
    if (tid == 0) sw[OB_RO] = bro[0];
    __syncthreads();

    const int b = blockIdx.x * THREADS + tid;
    if (b >= B) return;

    // scalar membrane states
    float m_sh[NSH], m_ch[NCH], m_co[NCO], m_rh[NRH], m_ro;
#pragma unroll
    for (int o = 0; o < NSH; o++) m_sh[o] = 0.0f;
#pragma unroll
    for (int o = 0; o < NCH; o++) m_ch[o] = 0.0f;
#pragma unroll
    for (int o = 0; o < NCO; o++) m_co[o] = 0.0f;
#pragma unroll
    for (int o = 0; o < NRH; o++) m_rh[o] = 0.0f;
    m_ro = 0.0f;

    const size_t TB = (size_t)TT * B;
    float* p_mco = out;                 // [T,B,3]
    float* p_sch = out + TB * 3;        // [T,B,8]
    float* p_mro = out + TB * 11;       // [T,B,1]
    float* p_srh = out + TB * 12;       // [T,B,14]
    float* p_ssh = out + TB * 26;       // [T,B,28]

    // register double-buffer for x: 32 floats = 8 float4
    float4 xc[8];
    {
        const float4* xp = (const float4*)(x + (size_t)b * NIN);
#pragma unroll
        for (int k = 0; k < 8; k++) xc[k] = __ldcs(xp + k);
    }

#pragma unroll 1
    for (int t = 0; t < TT; t++) {
        // prefetch next step's x into registers (off the critical path)
        float4 xn[8];
        if (t + 1 < TT) {
            const float4* xq = (const float4*)(x + ((size_t)(t + 1) * B + b) * NIN);
#pragma unroll
            for (int k = 0; k < 8; k++) xn[k] = __ldcs(xq + k);
        }

        // ---- Layer 1: shared hidden (28 <- 32), ascending i ----
        float sps[NSH];
#pragma unroll
        for (int o = 0; o < NSH; o++) {
            const float* wrow = &sw[OW_SH + o * NIN];
            float a = 0.0f;
#pragma unroll
            for (int k = 0; k < 8; k++) {
                float4 w = *(const float4*)(wrow + 4 * k);
                a = __fmaf_rn(xc[k].x, w.x, a);
                a = __fmaf_rn(xc[k].y, w.y, a);
                a = __fmaf_rn(xc[k].z, w.z, a);
                a = __fmaf_rn(xc[k].w, w.w, a);
            }
            sps[o] = lif(m_sh[o], a + sw[OB_SH + o]);
        }
        // store spk_sh: 28 floats at b*28 (112B stride -> 16B aligned)
        {
            float* p = p_ssh + ((size_t)t * B + b) * NSH;
#pragma unroll
            for (int k = 0; k < 7; k++)
                __stcs((float4*)p + k,
                       make_float4(sps[4 * k], sps[4 * k + 1], sps[4 * k + 2], sps[4 * k + 3]));
        }

        // ---- Layer 2: class hidden (8 <- 28) ----
        float spc[NCH];
#pragma unroll
        for (int o = 0; o < NCH; o++)
            spc[o] = lif(m_ch[o], dot28(sps, &sw[OW_CH + o * NSH]) + sw[OB_CH + o]);
        {
            float* p = p_sch + ((size_t)t * B + b) * NCH;
            __stcs((float4*)p,     make_float4(spc[0], spc[1], spc[2], spc[3]));
            __stcs((float4*)p + 1, make_float4(spc[4], spc[5], spc[6], spc[7]));
        }

        // ---- Layer 3: class out (3 <- 8), membrane recorded ----
        {
            float* p = p_mco + ((size_t)t * B + b) * NCO;
#pragma unroll
            for (int o = 0; o < NCO; o++) {
                const float* wrow = &sw[OW_CO + o * NCH];
                float a = 0.0f;
                float4 w0 = *(const float4*)(wrow);
                float4 w1 = *(const float4*)(wrow + 4);
                a = __fmaf_rn(spc[0], w0.x, a);
                a = __fmaf_rn(spc[1], w0.y, a);
                a = __fmaf_rn(spc[2], w0.z, a);
                a = __fmaf_rn(spc[3], w0.w, a);
                a = __fmaf_rn(spc[4], w1.x, a);
                a = __fmaf_rn(spc[5], w1.y, a);
                a = __fmaf_rn(spc[6], w1.z, a);
                a = __fmaf_rn(spc[7], w1.w, a);
                (void)lif(m_co[o], a + sw[OB_CO + o]);
                __stcs(p + o, m_co[o]);
            }
        }

        // ---- Layer 4: reg hidden (14 <- 28) ----
        float spr[NRH];
#pragma unroll
        for (int o = 0; o < NRH; o++)
            spr[o] = lif(m_rh[o], dot28(sps, &sw[OW_RH + o * NSH]) + sw[OB_RH + o]);
        {
            float* p = p_srh + ((size_t)t * B + b) * NRH;  // 56B stride -> 8B aligned
#pragma unroll
            for (int k = 0; k < 7; k++)
                __stcs((float2*)p + k, make_float2(spr[2 * k], spr[2 * k + 1]));
        }

        // ---- Layer 5: reg out (1 <- 14), membrane recorded ----
        {
            const float* wrow = &sw[OW_RO];
            float a = 0.0f;
            float4 w0 = *(const float4*)(wrow);
            float4 w1 = *(const float4*)(wrow + 4);
            float4 w2 = *(const float4*)(wrow + 8);
            float2 w3 = *(const float2*)(wrow + 12);
            a = __fmaf_rn(spr[0],  w0.x, a);
            a = __fmaf_rn(spr[1],  w0.y, a);
            a = __fmaf_rn(spr[2],  w0.z, a);
            a = __fmaf_rn(spr[3],  w0.w, a);
            a = __fmaf_rn(spr[4],  w1.x, a);
            a = __fmaf_rn(spr[5],  w1.y, a);
            a = __fmaf_rn(spr[6],  w1.z, a);
            a = __fmaf_rn(spr[7],  w1.w, a);
            a = __fmaf_rn(spr[8],  w2.x, a);
            a = __fmaf_rn(spr[9],  w2.y, a);
            a = __fmaf_rn(spr[10], w2.z, a);
            a = __fmaf_rn(spr[11], w2.w, a);
            a = __fmaf_rn(spr[12], w3.x, a);
            a = __fmaf_rn(spr[13], w3.y, a);
            (void)lif(m_ro, a + sw[OB_RO]);
            __stcs(p_mro + (size_t)t * B + b, m_ro);
        }

        // rotate x double-buffer
#pragma unroll
        for (int k = 0; k < 8; k++) xc[k] = xn[k];
    }
}

extern "C" void kernel_launch(void* const* d_in, const int* in_sizes, int n_in,
                              void* d_out, int out_size) {
    const float* x   = (const float*)d_in[0];
    const float* Wsh = (const float*)d_in[1];
    const float* bsh = (const float*)d_in[2];
    const float* Wch = (const float*)d_in[3];
    const float* bch = (const float*)d_in[4];
    const float* Wco = (const float*)d_in[5];
    const float* bco = (const float*)d_in[6];
    const float* Wrh = (const float*)d_in[7];
    const float* brh = (const float*)d_in[8];
    const float* Wro = (const float*)d_in[9];
    const float* bro = (const float*)d_in[10];

    const int B = in_sizes[0] / (TT * NIN);
    const int blocks = (B + THREADS - 1) / THREADS;

    snn_kernel<<<blocks, THREADS>>>(x, Wsh, bsh, Wch, bch, Wco, bco,
                                    Wrh, brh, Wro, bro, (float*)d_out, B);
}